// round 5
// baseline (speedup 1.0000x reference)
#include <cuda_runtime.h>
#include <cuda_fp16.h>
#include <math.h>
#include <stdint.h>

#define DM  256
#define SEQ 2304       // 48*48
#define NB  16

// Projected Q, K, V stored as fp16 (18 MB each)
__device__ __half g_Q[NB * SEQ * DM];
__device__ __half g_K[NB * SEQ * DM];
__device__ __half g_V[NB * SEQ * DM];

// ---------------------------------------------------------------------------
// helpers (sm_80-era PTX: legal on plain sm_103 target)
// ---------------------------------------------------------------------------
__device__ __forceinline__ uint32_t smem_u32(const void* p) {
    uint32_t a;
    asm("{ .reg .u64 t; cvta.to.shared.u64 t, %1; cvt.u32.u64 %0, t; }"
        : "=r"(a) : "l"(p));
    return a;
}
__device__ __forceinline__ void ldsm4(uint32_t* r, uint32_t addr) {
    asm volatile("ldmatrix.sync.aligned.m8n8.x4.shared.b16 {%0,%1,%2,%3}, [%4];"
        : "=r"(r[0]), "=r"(r[1]), "=r"(r[2]), "=r"(r[3]) : "r"(addr));
}
__device__ __forceinline__ void ldsm4t(uint32_t* r, uint32_t addr) {
    asm volatile("ldmatrix.sync.aligned.m8n8.x4.trans.shared.b16 {%0,%1,%2,%3}, [%4];"
        : "=r"(r[0]), "=r"(r[1]), "=r"(r[2]), "=r"(r[3]) : "r"(addr));
}
__device__ __forceinline__ void ldsm2t(uint32_t& r0, uint32_t& r1, uint32_t addr) {
    asm volatile("ldmatrix.sync.aligned.m8n8.x2.trans.shared.b16 {%0,%1}, [%2];"
        : "=r"(r0), "=r"(r1) : "r"(addr));
}
__device__ __forceinline__ void mma16816(float* c, const uint32_t* a,
                                         uint32_t b0, uint32_t b1) {
    asm volatile(
        "mma.sync.aligned.m16n8k16.row.col.f32.f16.f16.f32 "
        "{%0,%1,%2,%3},{%4,%5,%6,%7},{%8,%9},{%0,%1,%2,%3};"
        : "+f"(c[0]), "+f"(c[1]), "+f"(c[2]), "+f"(c[3])
        : "r"(a[0]), "r"(a[1]), "r"(a[2]), "r"(a[3]), "r"(b0), "r"(b1));
}
__device__ __forceinline__ uint32_t pack_h2(float lo, float hi) {
    uint32_t r;
    asm("cvt.rn.f16x2.f32 %0, %1, %2;" : "=r"(r) : "f"(hi), "f"(lo));
    return r;
}
#define CP_ASYNC16(dst, src) \
    asm volatile("cp.async.cg.shared.global [%0], [%1], 16;" \
                 :: "r"(dst), "l"(src) : "memory")
#define CP_COMMIT() asm volatile("cp.async.commit_group;" ::: "memory")
#define CP_WAIT0()  asm volatile("cp.async.wait_group 0;" ::: "memory")

// ---------------------------------------------------------------------------
// QKV: Y = (X+pos) @ W + b, fp16 out. (unchanged from R4 - known good)
// ---------------------------------------------------------------------------
#define ASTR 528                        // bytes per smem row (256h + 8h pad)
#define QKV_AS 0
#define QKV_WS (128 * ASTR)
#define QKV_SMEM (QKV_WS + 256 * ASTR)  // 202752

__global__ __launch_bounds__(256, 1) void qkv_mma(
    const float* __restrict__ x,  const float* __restrict__ pos,
    const float* __restrict__ wq, const float* __restrict__ bq,
    const float* __restrict__ wk, const float* __restrict__ bk,
    const float* __restrict__ wv, const float* __restrict__ bv)
{
    extern __shared__ char smem[];
    const uint32_t sb = smem_u32(smem);
    const int t = threadIdx.x, w = t >> 5, lane = t & 31;
    const int g = lane >> 2, tg = lane & 3;
    const int i8 = lane & 7, s1 = (lane >> 3) & 1, s2 = (lane >> 4) & 1;
    const int jj = lane & 15, ji = jj & 7, js = jj >> 3;

    const int wsel = blockIdx.y;
    const float* W    = (wsel == 0) ? wq : (wsel == 1) ? wk : wv;
    const float* bias = (wsel == 0) ? bq : (wsel == 1) ? bk : bv;
    __half*      outp = (wsel == 0) ? g_Q : (wsel == 1) ? g_K : g_V;

    const int m0 = blockIdx.x * 128;
    const int sbase = m0 % SEQ;

    #pragma unroll
    for (int p = 0; p < 32; p++) {
        int fid = p * 256 + t;
        int row = fid >> 6, c4 = fid & 63;
        float4 xa = *(const float4*)(x   + (size_t)(m0 + row) * DM + c4 * 4);
        float4 pa = *(const float4*)(pos + (size_t)(sbase + row) * DM + c4 * 4);
        uint2 u;
        u.x = pack_h2(xa.x + pa.x, xa.y + pa.y);
        u.y = pack_h2(xa.z + pa.z, xa.w + pa.w);
        *(uint2*)(smem + QKV_AS + row * ASTR + c4 * 8) = u;
    }
    #pragma unroll
    for (int p = 0; p < 64; p++) {
        int fid = p * 256 + t;
        int k = fid >> 6, c4 = fid & 63;
        float4 wv4 = *(const float4*)(W + (size_t)k * DM + c4 * 4);
        uint2 u;
        u.x = pack_h2(wv4.x, wv4.y);
        u.y = pack_h2(wv4.z, wv4.w);
        *(uint2*)(smem + QKV_WS + k * ASTR + c4 * 8) = u;
    }
    __syncthreads();

    const int wm2 = w & 1, wn2 = w >> 1;
    float acc[4][8][4] = {};

    const uint32_t abase = sb + QKV_AS + (64 * wm2 + i8 + s1 * 8) * ASTR + s2 * 16;
    const uint32_t bbase = sb + QKV_WS + (ji + js * 8) * ASTR + (64 * wn2) * 2;

    #pragma unroll
    for (int kk = 0; kk < 16; kk++) {
        uint32_t a[4][4];
        #pragma unroll
        for (int mi = 0; mi < 4; mi++)
            ldsm4(a[mi], abase + mi * 16 * ASTR + kk * 32);
        #pragma unroll
        for (int nt = 0; nt < 8; nt++) {
            uint32_t b0, b1;
            ldsm2t(b0, b1, bbase + kk * 16 * ASTR + nt * 16);
            #pragma unroll
            for (int mi = 0; mi < 4; mi++)
                mma16816(acc[mi][nt], a[mi], b0, b1);
        }
    }

    #pragma unroll
    for (int mi = 0; mi < 4; mi++) {
        int r0 = 64 * wm2 + 16 * mi + g;
        #pragma unroll
        for (int nt = 0; nt < 8; nt++) {
            int col = 64 * wn2 + 8 * nt + 2 * tg;
            float b0v = __ldg(bias + col), b1v = __ldg(bias + col + 1);
            *(uint32_t*)(outp + (size_t)(m0 + r0) * DM + col) =
                pack_h2(acc[mi][nt][0] + b0v, acc[mi][nt][1] + b1v);
            *(uint32_t*)(outp + (size_t)(m0 + r0 + 8) * DM + col) =
                pack_h2(acc[mi][nt][2] + b0v, acc[mi][nt][3] + b1v);
        }
    }
}

// ---------------------------------------------------------------------------
// Attention (FA2-style, register-resident P):
// CTA = 128 q rows x batch; warp w owns q-rows [16w, 16w+16), ALL cols.
// Per 64-token chunk: S (16x64) in regs -> exp -> A-fragments in regs ->
// O (16x256) accumulated in regs over all 36 chunks. One barrier per chunk.
// K and V both double-buffered via cp.async.
// ---------------------------------------------------------------------------
#define TOK 64
#define NCHUNK (SEQ / TOK)       // 36

#define AQ  0                        // Q [128][ASTR]   67584
#define AK0 (128 * ASTR)             // K buf0 [64][ASTR]
#define AK1 (AK0 + 64 * ASTR)
#define AV0 (AK1 + 64 * ASTR)
#define AV1 (AV0 + 64 * ASTR)
#define ATT_SMEM (AV1 + 64 * ASTR)   // 202752

__global__ __launch_bounds__(256, 1) void attn_mma(float* __restrict__ out)
{
    extern __shared__ char smem[];
    const uint32_t sb = smem_u32(smem);
    const int t = threadIdx.x, w = t >> 5, lane = t & 31;
    const int g = lane >> 2, tg = lane & 3;
    const int i8 = lane & 7, s1 = (lane >> 3) & 1, s2 = (lane >> 4) & 1;
    const int q4 = lane >> 3;   // 0..3: which 8x8 matrix this lane addresses

    const int qt = blockIdx.x, b = blockIdx.y;
    const __half* Qg = g_Q + ((size_t)b * SEQ + qt * 128) * DM;
    const __half* Kg = g_K + (size_t)b * SEQ * DM;
    const __half* Vg = g_V + (size_t)b * SEQ * DM;

    // prologue: Q tile + K0/V0
    #pragma unroll
    for (int p = 0; p < 16; p++) {
        int q = p * 256 + t;
        int row = q >> 5, gr = q & 31;
        CP_ASYNC16(sb + AQ + row * ASTR + gr * 16,
                   (const char*)Qg + row * 512 + gr * 16);
    }
    #pragma unroll
    for (int p = 0; p < 8; p++) {
        int q = p * 256 + t;
        int row = q >> 5, gr = q & 31;
        CP_ASYNC16(sb + AK0 + row * ASTR + gr * 16,
                   (const char*)Kg + row * 512 + gr * 16);
        CP_ASYNC16(sb + AV0 + row * ASTR + gr * 16,
                   (const char*)Vg + row * 512 + gr * 16);
    }
    CP_COMMIT();

    // A (Q) fragment base: rows 16w .. 16w+15
    const uint32_t qa_base = sb + AQ + (16 * w + i8 + s1 * 8) * ASTR + s2 * 16;
    // K B-frag (x4, two n-tiles): matrix q4 -> token (q4>>1)*8 + i8, k-half (q4&1)*16
    const uint32_t kb_lane = (uint32_t)(((q4 >> 1) * 8 + i8) * ASTR + (q4 & 1) * 16);
    // V B-frag (x4 trans, two d-tiles): token (q4&1)*8 + i8, d-col half (q4>>1)*16
    const uint32_t vb_lane = (uint32_t)((((q4 & 1) * 8 + i8)) * ASTR + (q4 >> 1) * 16);

    float oc[32][4] = {};        // O accum: 32 d-tiles x 4
    float rs0 = 0.0f, rs1 = 0.0f;
    const float scale = 0.0625f; // 1/sqrt(256)

    for (int kt = 0; kt < NCHUNK; kt++) {
        CP_WAIT0();
        __syncthreads();
        const uint32_t kbuf = sb + (kt & 1 ? AK1 : AK0);
        const uint32_t vbuf = sb + (kt & 1 ? AV1 : AV0);

        // prefetch next K/V into the other buffers (read last in chunk kt-1)
        if (kt + 1 < NCHUNK) {
            const __half* Kt = Kg + (size_t)(kt + 1) * TOK * DM;
            const __half* Vt = Vg + (size_t)(kt + 1) * TOK * DM;
            const uint32_t kdst = sb + ((kt + 1) & 1 ? AK1 : AK0);
            const uint32_t vdst = sb + ((kt + 1) & 1 ? AV1 : AV0);
            #pragma unroll
            for (int p = 0; p < 8; p++) {
                int q = p * 256 + t;
                int row = q >> 5, gr = q & 31;
                CP_ASYNC16(kdst + row * ASTR + gr * 16,
                           (const char*)Kt + row * 512 + gr * 16);
                CP_ASYNC16(vdst + row * ASTR + gr * 16,
                           (const char*)Vt + row * 512 + gr * 16);
            }
        }
        CP_COMMIT();

        // ---- S = Q K^T : rows 16w..+15, cols 0..63, K-dim 256 ----
        float sc[8][4] = {};
        #pragma unroll
        for (int kk = 0; kk < 16; kk++) {
            uint32_t a[4];
            ldsm4(a, qa_base + kk * 32);
            #pragma unroll
            for (int ntp = 0; ntp < 4; ntp++) {
                uint32_t bb[4];
                ldsm4(bb, kbuf + (uint32_t)(ntp * 16) * ASTR + kb_lane + kk * 32);
                mma16816(sc[2 * ntp],     a, bb[0], bb[1]);
                mma16816(sc[2 * ntp + 1], a, bb[2], bb[3]);
            }
        }

        // ---- exp -> A-fragments (in registers), accumulate rowsum ----
        uint32_t pfrag[4][4];
        #pragma unroll
        for (int c = 0; c < 4; c++) {
            float e00 = __expf(sc[2*c][0] * scale);
            float e01 = __expf(sc[2*c][1] * scale);
            float e02 = __expf(sc[2*c][2] * scale);
            float e03 = __expf(sc[2*c][3] * scale);
            float e10 = __expf(sc[2*c+1][0] * scale);
            float e11 = __expf(sc[2*c+1][1] * scale);
            float e12 = __expf(sc[2*c+1][2] * scale);
            float e13 = __expf(sc[2*c+1][3] * scale);
            rs0 += e00 + e01 + e10 + e11;
            rs1 += e02 + e03 + e12 + e13;
            pfrag[c][0] = pack_h2(e00, e01);   // row g,   k 0..7 cols
            pfrag[c][1] = pack_h2(e02, e03);   // row g+8, k 0..7
            pfrag[c][2] = pack_h2(e10, e11);   // row g,   k 8..15
            pfrag[c][3] = pack_h2(e12, e13);   // row g+8, k 8..15
        }

        // ---- O += P V : k-dim 64 tokens (4 steps), 256 d-cols ----
        #pragma unroll
        for (int kk2 = 0; kk2 < 4; kk2++) {
            #pragma unroll
            for (int np = 0; np < 16; np++) {
                uint32_t bb[4];
                ldsm4t(bb, vbuf + (uint32_t)(kk2 * 16) * ASTR + vb_lane + np * 32);
                mma16816(oc[2 * np],     pfrag[kk2], bb[0], bb[1]);
                mma16816(oc[2 * np + 1], pfrag[kk2], bb[2], bb[3]);
            }
        }
    }

    // ---- finalize: rowsum across the 4 tg lanes, divide, store ----
    rs0 += __shfl_xor_sync(0xffffffffu, rs0, 1);
    rs0 += __shfl_xor_sync(0xffffffffu, rs0, 2);
    rs1 += __shfl_xor_sync(0xffffffffu, rs1, 1);
    rs1 += __shfl_xor_sync(0xffffffffu, rs1, 2);
    const float inv0 = 1.0f / rs0, inv1 = 1.0f / rs1;

    float* ob = out + ((size_t)b * SEQ + qt * 128) * DM;
    const int row0 = 16 * w + g, row1 = row0 + 8;
    #pragma unroll
    for (int nt = 0; nt < 32; nt++) {
        int col = 8 * nt + 2 * tg;
        *(float2*)(ob + (size_t)row0 * DM + col) =
            make_float2(oc[nt][0] * inv0, oc[nt][1] * inv0);
        *(float2*)(ob + (size_t)row1 * DM + col) =
            make_float2(oc[nt][2] * inv1, oc[nt][3] * inv1);
    }
}

extern "C" void kernel_launch(void* const* d_in, const int* in_sizes, int n_in,
                              void* d_out, int out_size)
{
    const float* x   = (const float*)d_in[0];
    const float* wq  = (const float*)d_in[1];
    const float* bq  = (const float*)d_in[2];
    const float* wk  = (const float*)d_in[3];
    const float* bk  = (const float*)d_in[4];
    const float* wv  = (const float*)d_in[5];
    const float* bv  = (const float*)d_in[6];
    const float* pos = (const float*)d_in[7];
    float* out = (float*)d_out;

    cudaFuncSetAttribute(qkv_mma, cudaFuncAttributeMaxDynamicSharedMemorySize,
                         QKV_SMEM);
    cudaFuncSetAttribute(attn_mma, cudaFuncAttributeMaxDynamicSharedMemorySize,
                         ATT_SMEM);

    qkv_mma<<<dim3((NB * SEQ) / 128, 3), 256, QKV_SMEM>>>(
        x, pos, wq, bq, wk, bk, wv, bv);
    attn_mma<<<dim3(SEQ / 128, NB), 256, ATT_SMEM>>>(out);
}